// round 2
// baseline (speedup 1.0000x reference)
#include <cuda_runtime.h>
#include <cuda_bf16.h>
#include <cstdint>

#define FULL 0xFFFFFFFFu

static const int BB = 32;
static const int LL = 1024;
static const int DD = 1024;
static const int TT = 10;
static const int NROWS = BB * LL;           // 32768

// Scratch (device globals; no runtime allocation)
__device__ float4 g_W4[256 * 32];           // repacked weights: [d4][o], o padded to 32 (zeros)
__device__ float  g_Z[(size_t)NROWS * 32];  // per-row 30 dot products (padded to 32)
__device__ float  g_em[(size_t)NROWS * 10]; // emissions (log domain, incl. bias)
__device__ float  g_F[(size_t)NROWS * 10];  // exp(em - c)
__device__ float  g_c[NROWS];               // per-row max emission

// ---------------------------------------------------------------------------
// Repack conv_w (T, D, 3) -> W4[d4][o] float4 over d, o = t*3+k, zero-pad o>=30
// ---------------------------------------------------------------------------
__global__ void repack_w_kernel(const float* __restrict__ w) {
    int idx = blockIdx.x * blockDim.x + threadIdx.x;   // 8192 total
    int d4 = idx >> 5;
    int o  = idx & 31;
    float4 v = make_float4(0.f, 0.f, 0.f, 0.f);
    if (o < 30) {
        int t = o / 3, k = o % 3;
        int d = d4 * 4;
        v.x = w[((size_t)t * DD + d + 0) * 3 + k];
        v.y = w[((size_t)t * DD + d + 1) * 3 + k];
        v.z = w[((size_t)t * DD + d + 2) * 3 + k];
        v.w = w[((size_t)t * DD + d + 3) * 3 + k];
    }
    g_W4[d4 * 32 + o] = v;
}

// ---------------------------------------------------------------------------
// Z[row][o] = X[row] . W[o]   (lanes = outputs, 8 rows per warp, no reduction)
// ---------------------------------------------------------------------------
__global__ void __launch_bounds__(256) conv_z_kernel(const float* __restrict__ emb) {
    int warp = (blockIdx.x * blockDim.x + threadIdx.x) >> 5;
    int lane = threadIdx.x & 31;
    int row0 = warp * 8;

    const float4* __restrict__ X = reinterpret_cast<const float4*>(emb);
    const float4* base = X + (size_t)row0 * 256;

    float acc0 = 0.f, acc1 = 0.f, acc2 = 0.f, acc3 = 0.f;
    float acc4 = 0.f, acc5 = 0.f, acc6 = 0.f, acc7 = 0.f;

    #pragma unroll 2
    for (int d4 = 0; d4 < 256; ++d4) {
        float4 wv = __ldg(&g_W4[d4 * 32 + lane]);
        float4 x0 = __ldcs(base + 0 * 256 + d4);
        float4 x1 = __ldcs(base + 1 * 256 + d4);
        float4 x2 = __ldcs(base + 2 * 256 + d4);
        float4 x3 = __ldcs(base + 3 * 256 + d4);
        float4 x4 = __ldcs(base + 4 * 256 + d4);
        float4 x5 = __ldcs(base + 5 * 256 + d4);
        float4 x6 = __ldcs(base + 6 * 256 + d4);
        float4 x7 = __ldcs(base + 7 * 256 + d4);
        acc0 += wv.x * x0.x + wv.y * x0.y + wv.z * x0.z + wv.w * x0.w;
        acc1 += wv.x * x1.x + wv.y * x1.y + wv.z * x1.z + wv.w * x1.w;
        acc2 += wv.x * x2.x + wv.y * x2.y + wv.z * x2.z + wv.w * x2.w;
        acc3 += wv.x * x3.x + wv.y * x3.y + wv.z * x3.z + wv.w * x3.w;
        acc4 += wv.x * x4.x + wv.y * x4.y + wv.z * x4.z + wv.w * x4.w;
        acc5 += wv.x * x5.x + wv.y * x5.y + wv.z * x5.z + wv.w * x5.w;
        acc6 += wv.x * x6.x + wv.y * x6.y + wv.z * x6.z + wv.w * x6.w;
        acc7 += wv.x * x7.x + wv.y * x7.y + wv.z * x7.z + wv.w * x7.w;
    }
    float* z = &g_Z[(size_t)row0 * 32 + lane];
    z[0 * 32] = acc0; z[1 * 32] = acc1; z[2 * 32] = acc2; z[3 * 32] = acc3;
    z[4 * 32] = acc4; z[5 * 32] = acc5; z[6 * 32] = acc6; z[7 * 32] = acc7;
}

// ---------------------------------------------------------------------------
// Combine taps + bias -> em; compute c = max_t em, F = exp(em - c)
// ---------------------------------------------------------------------------
__global__ void combine_kernel(const float* __restrict__ conv_b) {
    int row = blockIdx.x * blockDim.x + threadIdx.x;   // < 32768
    int l = row & (LL - 1);
    const float* Zc = &g_Z[(size_t)row * 32];
    float e[10];
    #pragma unroll
    for (int t = 0; t < 10; ++t) {
        float v = conv_b[t] + Zc[t * 3 + 1];
        if (l > 0)      v += Zc[t * 3 - 32 + 0];  // Z0 of row-1
        if (l < LL - 1) v += Zc[t * 3 + 32 + 2];  // Z2 of row+1
        e[t] = v;
    }
    float c = e[0];
    #pragma unroll
    for (int t = 1; t < 10; ++t) c = fmaxf(c, e[t]);
    g_c[row] = c;
    #pragma unroll
    for (int t = 0; t < 10; ++t) {
        g_em[(size_t)row * 10 + t] = e[t];
        g_F[(size_t)row * 10 + t]  = __expf(e[t] - c);
    }
}

// ---------------------------------------------------------------------------
// CRF NLL: one warp per batch. Scaled forward algorithm (no per-step exp/log).
// ---------------------------------------------------------------------------
__global__ void crf_kernel(const int* __restrict__ mask,
                           const int* __restrict__ labels,
                           const float* __restrict__ start_t,
                           const float* __restrict__ end_t,
                           const float* __restrict__ trans,
                           float* __restrict__ out) {
    int b = blockIdx.x;
    int lane = threadIdx.x;
    int base = b * LL;
    bool act = (lane < TT);
    int j = act ? lane : 0;

    // ---------------- numerator ----------------
    float numv = 0.f;
    int slen = 0;
    for (int l = lane; l < LL; l += 32) {
        int m = __ldg(&mask[base + l]);
        slen += (m != 0);
        if (l > 0 && m) {
            int lp = __ldg(&labels[base + l - 1]);
            int lc = __ldg(&labels[base + l]);
            numv += __ldg(&trans[lp * TT + lc]) + g_em[(size_t)(base + l) * 10 + lc];
        }
    }
    if (lane == 0) {
        int l0 = __ldg(&labels[base]);
        numv += __ldg(&start_t[l0]) + g_em[(size_t)base * 10 + l0];
    }
    #pragma unroll
    for (int off = 16; off; off >>= 1) {
        numv += __shfl_xor_sync(FULL, numv, off);
        slen += __shfl_xor_sync(FULL, slen, off);
    }
    int last = __ldg(&labels[base + slen - 1]);
    numv += __ldg(&end_t[last]);

    // ---------------- denominator: scaled forward ----------------
    float E[10];
    #pragma unroll
    for (int i = 0; i < 10; ++i)
        E[i] = act ? __expf(__ldg(&trans[i * TT + j])) : 0.f;

    float q = act ? __expf(__ldg(&start_t[j])) * g_F[(size_t)base * 10 + j] : 0.f;
    float logZ = g_c[base];

    // 64 chunks of 16 steps; prefetch each chunk's F/c/mask as a batch (MLP=48)
    for (int ch = 0; ch < 64; ++ch) {
        int l0 = ch * 16;
        float fb[16], cb[16];
        int mb[16];
        #pragma unroll
        for (int k = 0; k < 16; ++k) {
            int l = l0 + k;
            fb[k] = act ? __ldg(&g_F[(size_t)(base + l) * 10 + j]) : 0.f;
            cb[k] = __ldg(&g_c[base + l]);
            mb[k] = __ldg(&mask[base + l]);
        }
        #pragma unroll
        for (int k = 0; k < 16; ++k) {
            int l = l0 + k;
            if (l == 0) continue;   // step 0 is the init
            float v0 = 0.f, v1 = 0.f;
            #pragma unroll
            for (int i = 0; i < 5; ++i)
                v0 = fmaf(__shfl_sync(FULL, q, i), E[i], v0);
            #pragma unroll
            for (int i = 5; i < 10; ++i)
                v1 = fmaf(__shfl_sync(FULL, q, i), E[i], v1);
            if (mb[k]) {            // mask uniform across warp
                q = (v0 + v1) * fb[k];
                logZ += cb[k];
            }
        }
        // renormalize
        float s = q;
        #pragma unroll
        for (int off = 16; off; off >>= 1) s += __shfl_xor_sync(FULL, s, off);
        logZ += __logf(s);
        q *= (1.0f / s);
    }

    float r = act ? q * __expf(__ldg(&end_t[j])) : 0.f;
    #pragma unroll
    for (int off = 16; off; off >>= 1) r += __shfl_xor_sync(FULL, r, off);
    float denom = logZ + __logf(r);

    if (lane == 0) atomicAdd(out, -(numv - denom));
}

// ---------------------------------------------------------------------------
extern "C" void kernel_launch(void* const* d_in, const int* in_sizes, int n_in,
                              void* d_out, int out_size) {
    const float* emb     = (const float*)d_in[0];  // (32,1024,1024) f32
    const int*   mask    = (const int*)  d_in[1];  // (32,1024) i32
    const int*   labels  = (const int*)  d_in[2];  // (32,1024) i32
    const float* conv_w  = (const float*)d_in[3];  // (10,1024,3)
    const float* conv_b  = (const float*)d_in[4];  // (10,)
    const float* start_t = (const float*)d_in[5];  // (10,)
    const float* end_t   = (const float*)d_in[6];  // (10,)
    const float* trans   = (const float*)d_in[7];  // (10,10)
    float* out = (float*)d_out;

    cudaMemsetAsync(out, 0, sizeof(float));

    repack_w_kernel<<<32, 256>>>(conv_w);
    conv_z_kernel<<<512, 256>>>(emb);          // 4096 warps x 8 rows
    combine_kernel<<<NROWS / 256, 256>>>(conv_b);
    crf_kernel<<<BB, 32>>>(mask, labels, start_t, end_t, trans, out);
}

// round 3
// speedup vs baseline: 1.3115x; 1.3115x over previous
#include <cuda_runtime.h>
#include <cuda_bf16.h>
#include <cstdint>

#define FULL 0xFFFFFFFFu
typedef unsigned long long u64;

static const int BB = 32;
static const int LL = 1024;
static const int DD = 1024;
static const int TT = 10;
static const int NROWS = BB * LL;           // 32768
static const int NSEG  = 16;                // segments per sequence
static const int SEGL  = 64;                // steps per segment

// Scratch (device globals; no runtime allocation)
__device__ float4 g_W4[256 * 32];           // repacked weights: [d4][o], o padded to 32
__device__ float  g_Z[(size_t)NROWS * 32];  // per-row 30 dot products (padded to 32)
__device__ float  g_em[(size_t)NROWS * 10]; // emissions (log domain, incl. bias)
__device__ float  g_F[(size_t)NROWS * 10];  // exp(em - c)
__device__ float  g_c[NROWS];               // per-row max emission
__device__ float  g_M[BB][NSEG][10][10];    // segment transfer: [b][s][col c][j]
__device__ float  g_sig[BB][NSEG][10];      // per-column log scale
__device__ float  g_cs[BB][NSEG];           // sum of c_l over masked steps in segment

__device__ __forceinline__ void ffma2(u64 &d, u64 a, u64 b) {
    asm("fma.rn.f32x2 %0, %1, %2, %0;" : "+l"(d) : "l"(a), "l"(b));
}

// ---------------------------------------------------------------------------
// Repack conv_w (T, D, 3) -> W4[d4][o] float4 over d, o = t*3+k, zero-pad o>=30
// ---------------------------------------------------------------------------
__global__ void repack_w_kernel(const float* __restrict__ w) {
    int idx = blockIdx.x * blockDim.x + threadIdx.x;   // 8192 total
    int d4 = idx >> 5;
    int o  = idx & 31;
    float4 v = make_float4(0.f, 0.f, 0.f, 0.f);
    if (o < 30) {
        int t = o / 3, k = o % 3;
        int d = d4 * 4;
        v.x = w[((size_t)t * DD + d + 0) * 3 + k];
        v.y = w[((size_t)t * DD + d + 1) * 3 + k];
        v.z = w[((size_t)t * DD + d + 2) * 3 + k];
        v.w = w[((size_t)t * DD + d + 3) * 3 + k];
    }
    g_W4[d4 * 32 + o] = v;
}

// ---------------------------------------------------------------------------
// Z[row][o] = X[row].W[o] — lanes = outputs, 8 rows/warp, packed f32x2 math.
// float4 = two aligned f32x2 pairs -> zero-cost packing for fma.rn.f32x2.
// ---------------------------------------------------------------------------
__global__ void __launch_bounds__(256) conv_z_kernel(const float* __restrict__ emb) {
    int warp = (blockIdx.x * blockDim.x + threadIdx.x) >> 5;
    int lane = threadIdx.x & 31;
    int row0 = warp * 8;

    const double2* __restrict__ X = reinterpret_cast<const double2*>(emb);
    const double2* __restrict__ W = reinterpret_cast<const double2*>(g_W4);
    const double2* base = X + (size_t)row0 * 256;

    u64 a0 = 0ull, a1 = 0ull, a2 = 0ull, a3 = 0ull;
    u64 a4 = 0ull, a5 = 0ull, a6 = 0ull, a7 = 0ull;

    #pragma unroll 2
    for (int d4 = 0; d4 < 256; ++d4) {
        double2 wv = __ldg(&W[d4 * 32 + lane]);
        u64 wlo = __double_as_longlong(wv.x);
        u64 whi = __double_as_longlong(wv.y);
        double2 x0 = __ldcs(base + 0 * 256 + d4);
        double2 x1 = __ldcs(base + 1 * 256 + d4);
        double2 x2 = __ldcs(base + 2 * 256 + d4);
        double2 x3 = __ldcs(base + 3 * 256 + d4);
        double2 x4 = __ldcs(base + 4 * 256 + d4);
        double2 x5 = __ldcs(base + 5 * 256 + d4);
        double2 x6 = __ldcs(base + 6 * 256 + d4);
        double2 x7 = __ldcs(base + 7 * 256 + d4);
        ffma2(a0, wlo, __double_as_longlong(x0.x)); ffma2(a0, whi, __double_as_longlong(x0.y));
        ffma2(a1, wlo, __double_as_longlong(x1.x)); ffma2(a1, whi, __double_as_longlong(x1.y));
        ffma2(a2, wlo, __double_as_longlong(x2.x)); ffma2(a2, whi, __double_as_longlong(x2.y));
        ffma2(a3, wlo, __double_as_longlong(x3.x)); ffma2(a3, whi, __double_as_longlong(x3.y));
        ffma2(a4, wlo, __double_as_longlong(x4.x)); ffma2(a4, whi, __double_as_longlong(x4.y));
        ffma2(a5, wlo, __double_as_longlong(x5.x)); ffma2(a5, whi, __double_as_longlong(x5.y));
        ffma2(a6, wlo, __double_as_longlong(x6.x)); ffma2(a6, whi, __double_as_longlong(x6.y));
        ffma2(a7, wlo, __double_as_longlong(x7.x)); ffma2(a7, whi, __double_as_longlong(x7.y));
    }
    float* z = &g_Z[(size_t)row0 * 32 + lane];
    float2 f;
    f = *reinterpret_cast<float2*>(&a0); z[0 * 32] = f.x + f.y;
    f = *reinterpret_cast<float2*>(&a1); z[1 * 32] = f.x + f.y;
    f = *reinterpret_cast<float2*>(&a2); z[2 * 32] = f.x + f.y;
    f = *reinterpret_cast<float2*>(&a3); z[3 * 32] = f.x + f.y;
    f = *reinterpret_cast<float2*>(&a4); z[4 * 32] = f.x + f.y;
    f = *reinterpret_cast<float2*>(&a5); z[5 * 32] = f.x + f.y;
    f = *reinterpret_cast<float2*>(&a6); z[6 * 32] = f.x + f.y;
    f = *reinterpret_cast<float2*>(&a7); z[7 * 32] = f.x + f.y;
}

// ---------------------------------------------------------------------------
// Combine taps + bias -> em; compute c = max_t em, F = exp(em - c)
// ---------------------------------------------------------------------------
__global__ void combine_kernel(const float* __restrict__ conv_b) {
    int row = blockIdx.x * blockDim.x + threadIdx.x;   // < 32768
    int l = row & (LL - 1);
    const float* Zc = &g_Z[(size_t)row * 32];
    float e[10];
    #pragma unroll
    for (int t = 0; t < 10; ++t) {
        float v = conv_b[t] + Zc[t * 3 + 1];
        if (l > 0)      v += Zc[t * 3 - 32 + 0];  // Z0 of row-1
        if (l < LL - 1) v += Zc[t * 3 + 32 + 2];  // Z2 of row+1
        e[t] = v;
    }
    float c = e[0];
    #pragma unroll
    for (int t = 1; t < 10; ++t) c = fmaxf(c, e[t]);
    g_c[row] = c;
    #pragma unroll
    for (int t = 0; t < 10; ++t) {
        g_em[(size_t)row * 10 + t] = e[t];
        g_F[(size_t)row * 10 + t]  = __expf(e[t] - c);
    }
}

// ---------------------------------------------------------------------------
// CRF segment scan: compute per-segment 10x10 transfer matrices by propagating
// basis vectors. Block = one (batch, segment): 4 warps x 3 basis columns.
// Lane layout: lane = grp*10 + j (grp 0..2, lanes 30/31 idle).
// ---------------------------------------------------------------------------
__global__ void __launch_bounds__(128) crf_seg_kernel(
        const int* __restrict__ mask, const float* __restrict__ trans) {
    int seg  = blockIdx.x & (NSEG - 1);
    int b    = blockIdx.x >> 4;
    int w    = threadIdx.x >> 5;      // warp in segment, 0..3
    int lane = threadIdx.x & 31;
    int grp  = lane / 10;             // 0..3 (3 => junk lanes)
    bool act = lane < 30;
    int j    = act ? (lane - grp * 10) : 0;
    int colv = w * 3 + (act ? grp : 0);
    bool store = act && colv < 10;
    int base_lane = act ? grp * 10 : 0;
    int base = b * LL;

    float E[10];
    #pragma unroll
    for (int i = 0; i < 10; ++i)
        E[i] = act ? __expf(__ldg(&trans[i * TT + j])) : 0.f;

    // basis vector e_col (clamped to e_0 for non-stored columns)
    int tgt = store ? colv : 0;
    float q = (act && j == tgt) ? 1.f : 0.f;
    float sig = 0.f, cs = 0.f;

    int l0 = seg * SEGL;
    for (int ch = 0; ch < SEGL / 16; ++ch) {
        float fb[16], cb[16];
        int mb[16];
        #pragma unroll
        for (int k = 0; k < 16; ++k) {
            int l = l0 + ch * 16 + k + 1;
            bool valid = l < LL;
            fb[k] = (act && valid) ? __ldg(&g_F[(size_t)(base + l) * 10 + j]) : 1.f;
            cb[k] = valid ? __ldg(&g_c[base + l]) : 0.f;
            mb[k] = valid ? __ldg(&mask[base + l]) : 0;
        }
        #pragma unroll
        for (int k = 0; k < 16; ++k) {
            float v0 = 0.f, v1 = 0.f;
            #pragma unroll
            for (int i = 0; i < 5; ++i)
                v0 = fmaf(__shfl_sync(FULL, q, base_lane + i), E[i], v0);
            #pragma unroll
            for (int i = 5; i < 10; ++i)
                v1 = fmaf(__shfl_sync(FULL, q, base_lane + i), E[i], v1);
            if (mb[k]) {                 // uniform across warp
                q = (v0 + v1) * fb[k];
                cs += cb[k];
            }
        }
        // renormalize per basis group
        float s = 0.f;
        #pragma unroll
        for (int i = 0; i < 10; ++i)
            s += __shfl_sync(FULL, q, base_lane + i);
        sig += __logf(s);
        q *= (1.0f / s);
    }

    if (store) {
        g_M[b][seg][colv][j] = q;
        if (j == 0) g_sig[b][seg][colv] = sig;
    }
    if (threadIdx.x == 0) g_cs[b][seg] = cs;
}

// ---------------------------------------------------------------------------
// CRF combine: one warp per batch. Numerator + sequential segment matvecs.
// ---------------------------------------------------------------------------
__global__ void crf_combine_kernel(const int* __restrict__ mask,
                                   const int* __restrict__ labels,
                                   const float* __restrict__ start_t,
                                   const float* __restrict__ end_t,
                                   const float* __restrict__ trans,
                                   float* __restrict__ out) {
    int b = blockIdx.x;
    int lane = threadIdx.x;
    int base = b * LL;
    bool act = (lane < TT);
    int j = act ? lane : 0;

    // ---------------- numerator ----------------
    float numv = 0.f;
    int slen = 0;
    for (int l = lane; l < LL; l += 32) {
        int m = __ldg(&mask[base + l]);
        slen += (m != 0);
        if (l > 0 && m) {
            int lp = __ldg(&labels[base + l - 1]);
            int lc = __ldg(&labels[base + l]);
            numv += __ldg(&trans[lp * TT + lc]) + g_em[(size_t)(base + l) * 10 + lc];
        }
    }
    if (lane == 0) {
        int l0 = __ldg(&labels[base]);
        numv += __ldg(&start_t[l0]) + g_em[(size_t)base * 10 + l0];
    }
    #pragma unroll
    for (int off = 16; off; off >>= 1) {
        numv += __shfl_xor_sync(FULL, numv, off);
        slen += __shfl_xor_sync(FULL, slen, off);
    }
    int last = __ldg(&labels[base + slen - 1]);
    numv += __ldg(&end_t[last]);

    // ---------------- denominator: apply 16 segment matrices ----------------
    float q = act ? __expf(__ldg(&start_t[j])) * g_F[(size_t)base * 10 + j] : 0.f;
    float logA = g_c[base];

    for (int s = 0; s < NSEG; ++s) {
        // prefetch M column slice for this lane's j
        float mrow[10];
        #pragma unroll
        for (int c = 0; c < 10; ++c)
            mrow[c] = act ? __ldg(&g_M[b][s][c][j]) : 0.f;
        float sg = (lane < 10) ? __ldg(&g_sig[b][s][lane]) : -1e30f;
        float sm = sg;
        #pragma unroll
        for (int off = 16; off; off >>= 1)
            sm = fmaxf(sm, __shfl_xor_sync(FULL, sm, off));
        float u = act ? q * __expf(sg - sm) : 0.f;   // note: lane j holds q_j, sig_j
        float v = 0.f;
        #pragma unroll
        for (int c = 0; c < 10; ++c)
            v = fmaf(__shfl_sync(FULL, u, c), mrow[c], v);
        q = v;
        logA += sm + __ldg(&g_cs[b][s]);
        float ssum = q;
        #pragma unroll
        for (int off = 16; off; off >>= 1)
            ssum += __shfl_xor_sync(FULL, ssum, off);
        logA += __logf(ssum);
        q *= (1.0f / ssum);
    }

    float r = act ? q * __expf(__ldg(&end_t[j])) : 0.f;
    #pragma unroll
    for (int off = 16; off; off >>= 1) r += __shfl_xor_sync(FULL, r, off);
    float denom = logA + __logf(r);

    if (lane == 0) atomicAdd(out, -(numv - denom));
}

// ---------------------------------------------------------------------------
extern "C" void kernel_launch(void* const* d_in, const int* in_sizes, int n_in,
                              void* d_out, int out_size) {
    const float* emb     = (const float*)d_in[0];  // (32,1024,1024) f32
    const int*   mask    = (const int*)  d_in[1];  // (32,1024) i32
    const int*   labels  = (const int*)  d_in[2];  // (32,1024) i32
    const float* conv_w  = (const float*)d_in[3];  // (10,1024,3)
    const float* conv_b  = (const float*)d_in[4];  // (10,)
    const float* start_t = (const float*)d_in[5];  // (10,)
    const float* end_t   = (const float*)d_in[6];  // (10,)
    const float* trans   = (const float*)d_in[7];  // (10,10)
    float* out = (float*)d_out;

    cudaMemsetAsync(out, 0, sizeof(float));

    repack_w_kernel<<<32, 256>>>(conv_w);
    conv_z_kernel<<<512, 256>>>(emb);                 // 4096 warps x 8 rows
    combine_kernel<<<NROWS / 256, 256>>>(conv_b);
    crf_seg_kernel<<<BB * NSEG, 128>>>(mask, trans);  // 2048 warps
    crf_combine_kernel<<<BB, 32>>>(mask, labels, start_t, end_t, trans, out);
}